// round 1
// baseline (speedup 1.0000x reference)
#include <cuda_runtime.h>
#include <math.h>

#define NN  128000   // B*NPG nodes
#define EE  2048000  // B*EPG edges
#define BBG 128      // graphs
#define NPG 1000
#define EPG 16000
#define DD  128
#define KK  64

// ---------------- scratch (static device globals; no allocs) ----------------
__device__ int   g_deg[NN];
__device__ float g_dinv[NN];
__device__ int   g_rowptr[NN];
__device__ int   g_cursor[NN];
__device__ int   g_csr_src[EE];
__device__ float g_csr_val[EE];
__device__ float g_bufA[(size_t)NN * DD];
__device__ float g_bufB[(size_t)NN * DD];
__device__ float g_pool[BBG * DD];

// ---------------- degree count ----------------
__global__ void k_zero_deg(int n) {
    int i = blockIdx.x * blockDim.x + threadIdx.x;
    if (i < n) g_deg[i] = 0;
}

__global__ void k_count_deg(const int* __restrict__ dst, int E) {
    int e = blockIdx.x * blockDim.x + threadIdx.x;
    if (e < E) atomicAdd(&g_deg[dst[e]], 1);
}

// ---------------- per-graph exclusive scan -> rowptr/cursor, dinv ----------------
// grid = BBG blocks, 1024 threads. Each graph has exactly EPG edges, so graph b's
// CSR slots are [b*EPG, (b+1)*EPG).
__global__ void k_scan(void) {
    int b = blockIdx.x;
    int t = threadIdx.x;
    int v = b * NPG + t;
    int val = (t < NPG) ? g_deg[v] : 0;

    // warp inclusive scan
    int x = val;
    unsigned m = 0xffffffffu;
    #pragma unroll
    for (int o = 1; o < 32; o <<= 1) {
        int y = __shfl_up_sync(m, x, o);
        if ((t & 31) >= o) x += y;
    }
    __shared__ int ws[32];
    if ((t & 31) == 31) ws[t >> 5] = x;
    __syncthreads();
    if (t < 32) {
        int y = ws[t];
        int z = y;
        #pragma unroll
        for (int o = 1; o < 32; o <<= 1) {
            int w = __shfl_up_sync(m, z, o);
            if (t >= o) z += w;
        }
        ws[t] = z - y;  // exclusive warp-sum prefix
    }
    __syncthreads();
    int incl = x + ws[t >> 5];
    int excl = incl - val;
    if (t < NPG) {
        int base = b * EPG;
        g_rowptr[v] = base + excl;
        g_cursor[v] = base + excl;
        g_dinv[v] = 1.0f / sqrtf((float)(val + 1));  // +1 self-loop
    }
}

// ---------------- CSR fill (src idx + dinv[src] per edge) ----------------
__global__ void k_fill_csr(const int* __restrict__ src, const int* __restrict__ dst, int E) {
    int e = blockIdx.x * blockDim.x + threadIdx.x;
    if (e < E) {
        int s = src[e];
        int d = dst[e];
        int p = atomicAdd(&g_cursor[d], 1);
        g_csr_src[p] = s;
        g_csr_val[p] = g_dinv[s];
    }
}

// ---------------- SIMT GEMM: O[N,128] = X[N,128] @ W[128,128] ----------------
// Block: 256 threads, tile 64 rows x 128 cols. W (64KB) + X tile (32KB) in smem.
__global__ void k_gemm128(const float* __restrict__ X, const float* __restrict__ W,
                          float* __restrict__ O) {
    extern __shared__ float sm[];
    float* sW = sm;             // 128*128
    float* sX = sm + DD * DD;   // 64*128
    int t = threadIdx.x;
    size_t row0 = (size_t)blockIdx.x * 64;

    const float4* W4 = (const float4*)W;
    float4* sW4 = (float4*)sW;
    #pragma unroll
    for (int i = t; i < DD * DD / 4; i += 256) sW4[i] = W4[i];
    const float4* X4 = (const float4*)(X + row0 * DD);
    float4* sX4 = (float4*)sX;
    #pragma unroll
    for (int i = t; i < 64 * DD / 4; i += 256) sX4[i] = X4[i];
    __syncthreads();

    int tx = t & 31;   // col group: cols tx*4 .. tx*4+3
    int ty = t >> 5;   // row group: rows ty*8 .. ty*8+7
    float4 acc[8];
    #pragma unroll
    for (int r = 0; r < 8; r++) acc[r] = make_float4(0.f, 0.f, 0.f, 0.f);

    const float* xb = sX + (ty * 8) * DD;
    const float4* sWr = (const float4*)sW;

    #pragma unroll 2
    for (int k = 0; k < DD; k += 4) {
        float4 w0 = sWr[(k + 0) * 32 + tx];
        float4 w1 = sWr[(k + 1) * 32 + tx];
        float4 w2 = sWr[(k + 2) * 32 + tx];
        float4 w3 = sWr[(k + 3) * 32 + tx];
        #pragma unroll
        for (int r = 0; r < 8; r++) {
            float4 xv = *(const float4*)&xb[r * DD + k];
            acc[r].x += xv.x * w0.x; acc[r].y += xv.x * w0.y; acc[r].z += xv.x * w0.z; acc[r].w += xv.x * w0.w;
            acc[r].x += xv.y * w1.x; acc[r].y += xv.y * w1.y; acc[r].z += xv.y * w1.z; acc[r].w += xv.y * w1.w;
            acc[r].x += xv.z * w2.x; acc[r].y += xv.z * w2.y; acc[r].z += xv.z * w2.z; acc[r].w += xv.z * w2.w;
            acc[r].x += xv.w * w3.x; acc[r].y += xv.w * w3.y; acc[r].z += xv.w * w3.z; acc[r].w += xv.w * w3.w;
        }
    }

    #pragma unroll
    for (int r = 0; r < 8; r++) {
        ((float4*)(O + (row0 + ty * 8 + r) * DD))[tx] = acc[r];
    }
}

// ---------------- aggregation: OUT[v] = dinv[v]*(dinv[v]*XW[v] + sum_e dinv[s]*XW[s]) + b ----
// One warp per node; lane owns 4 dims (float4). No atomics; CSR gather.
__global__ void k_aggregate(const float* __restrict__ XW, float* __restrict__ OUT,
                            const float* __restrict__ bias, int do_relu) {
    int warp = (blockIdx.x * blockDim.x + threadIdx.x) >> 5;
    int lane = threadIdx.x & 31;
    if (warp >= NN) return;
    int v = warp;

    const float4* X4 = (const float4*)XW;
    float dv = g_dinv[v];
    float4 a = X4[(size_t)v * 32 + lane];
    float4 acc = make_float4(dv * a.x, dv * a.y, dv * a.z, dv * a.w);

    int start = g_rowptr[v];
    int cnt = g_deg[v];
    for (int base = 0; base < cnt; base += 32) {
        int idx = base + lane;
        int s = 0;
        float c = 0.f;
        if (idx < cnt) {
            s = g_csr_src[start + idx];
            c = g_csr_val[start + idx];
        }
        int mcnt = min(32, cnt - base);
        int j = 0;
        for (; j + 4 <= mcnt; j += 4) {
            #pragma unroll
            for (int u = 0; u < 4; u++) {
                int   sj = __shfl_sync(0xffffffffu, s, j + u);
                float cj = __shfl_sync(0xffffffffu, c, j + u);
                float4 xs = X4[(size_t)sj * 32 + lane];
                acc.x += cj * xs.x; acc.y += cj * xs.y;
                acc.z += cj * xs.z; acc.w += cj * xs.w;
            }
        }
        for (; j < mcnt; j++) {
            int   sj = __shfl_sync(0xffffffffu, s, j);
            float cj = __shfl_sync(0xffffffffu, c, j);
            float4 xs = X4[(size_t)sj * 32 + lane];
            acc.x += cj * xs.x; acc.y += cj * xs.y;
            acc.z += cj * xs.z; acc.w += cj * xs.w;
        }
    }

    float4 bb = ((const float4*)bias)[lane];
    float4 res = make_float4(dv * acc.x + bb.x, dv * acc.y + bb.y,
                             dv * acc.z + bb.z, dv * acc.w + bb.w);
    if (do_relu) {
        res.x = fmaxf(res.x, 0.f); res.y = fmaxf(res.y, 0.f);
        res.z = fmaxf(res.z, 0.f); res.w = fmaxf(res.w, 0.f);
    }
    ((float4*)OUT)[(size_t)v * 32 + lane] = res;
}

// ---------------- per-graph mean pool / K ----------------
// grid = 128 blocks (one per graph), 512 threads: 4 partial sums per dim.
__global__ void k_pool(const float* __restrict__ NE) {
    int b = blockIdx.x;
    int t = threadIdx.x;
    int dd = t & 127;
    int q = t >> 7;  // 0..3
    const float* base = NE + (size_t)b * NPG * DD + dd;
    float s = 0.f;
    int r0 = q * (NPG / 4);
    #pragma unroll 4
    for (int r = 0; r < NPG / 4; r++) s += base[(size_t)(r0 + r) * DD];
    __shared__ float sm[512];
    sm[t] = s;
    __syncthreads();
    if (q == 0) {
        float tot = sm[dd] + sm[dd + 128] + sm[dd + 256] + sm[dd + 384];
        g_pool[b * DD + dd] = tot * (1.0f / KK);
    }
}

// ---------------- final MLP: relu(pool@W1+b1)@W2+b2 ----------------
__global__ void k_mlp(const float* __restrict__ W1, const float* __restrict__ b1,
                      const float* __restrict__ W2, const float* __restrict__ b2,
                      float* __restrict__ out) {
    int b = blockIdx.x;
    int t = threadIdx.x;  // 128
    __shared__ float p[128], h[128];
    p[t] = g_pool[b * 128 + t];
    __syncthreads();
    float acc = b1[t];
    #pragma unroll 4
    for (int d = 0; d < 128; d++) acc += p[d] * W1[d * 128 + t];
    h[t] = fmaxf(acc, 0.f);
    __syncthreads();
    if (t < 10) {
        float o = b2[t];
        #pragma unroll 4
        for (int j = 0; j < 128; j++) o += h[j] * W2[j * 10 + t];
        out[b * 10 + t] = o;
    }
}

// ---------------- launch ----------------
extern "C" void kernel_launch(void* const* d_in, const int* in_sizes, int n_in,
                              void* d_out, int out_size) {
    const float* x     = (const float*)d_in[0];
    const int*   ei    = (const int*)d_in[1];
    const float* W_pre = (const float*)d_in[3];
    const float* b_pre = (const float*)d_in[4];
    const float* W_emb = (const float*)d_in[5];
    const float* b_emb = (const float*)d_in[6];
    // d_in[2] batch, d_in[7] W_asn, d_in[8] b_asn are provably dead (softmax rows sum to 1)
    const float* W1 = (const float*)d_in[9];
    const float* b1 = (const float*)d_in[10];
    const float* W2 = (const float*)d_in[11];
    const float* b2 = (const float*)d_in[12];
    float* out = (float*)d_out;

    int E = in_sizes[1] / 2;
    int N = in_sizes[0] / DD;
    const int* src = ei;
    const int* dst = ei + E;

    void *pA, *pB;
    cudaGetSymbolAddress(&pA, g_bufA);
    cudaGetSymbolAddress(&pB, g_bufB);
    float* bufA = (float*)pA;
    float* bufB = (float*)pB;

    const int smem_gemm = (DD * DD + 64 * DD) * (int)sizeof(float);  // 96KB
    cudaFuncSetAttribute(k_gemm128, cudaFuncAttributeMaxDynamicSharedMemorySize, smem_gemm);

    // build normalized-adjacency CSR (by dst)
    k_zero_deg<<<(N + 255) / 256, 256>>>(N);
    k_count_deg<<<(E + 255) / 256, 256>>>(dst, E);
    k_scan<<<BBG, 1024>>>();
    k_fill_csr<<<(E + 255) / 256, 256>>>(src, dst, E);

    // conv1: h = relu(Ahat @ (x @ W_pre) + b_pre)
    k_gemm128<<<N / 64, 256, smem_gemm>>>(x, W_pre, bufA);
    k_aggregate<<<N / 8, 256>>>(bufA, bufB, b_pre, 1);

    // conv2: NE = relu(Ahat @ (h @ W_emb) + b_emb)
    k_gemm128<<<N / 64, 256, smem_gemm>>>(bufB, W_emb, bufA);
    k_aggregate<<<N / 8, 256>>>(bufA, bufB, b_emb, 1);

    // pool (softmax-assignment branch collapses to mean/K) + MLP head
    k_pool<<<BBG, 512>>>(bufB);
    k_mlp<<<BBG, 128>>>(W1, b1, W2, b2, out);
}